// round 12
// baseline (speedup 1.0000x reference)
#include <cuda_runtime.h>
#include <math.h>

#define BATCH 64
#define SEQ   512
#define EMB   512
#define HID   1024
#define BH    (BATCH * HID)        // 65536
#define SBH   (SEQ * BH)           // 33554432
#define KSLICES 8
#define NBLOCKS 128                // 16 h-tiles (64h) x 8 k-slices (128k)

// smem: Ws[128][64] (32 KB) + 8 warp-private As[128][8] (32 KB)
#define RNN_SMEM ((128 * 64 + 8 * 128 * 8) * 4)

typedef unsigned long long u64;

// Per-step K-split partials: [KSLICES][BATCH][HID] = 2 MB
__device__ float g_partial[KSLICES * BH];
// Counters: ca[g][w] at (g*8+w)*16, cp[g][w] at 2048+(g*8+w)*16 (64B apart)
__device__ unsigned g_sync[4096];

// ---------------- packed fp32x2 helpers (sm_103a) ---------------------------
__device__ __forceinline__ u64 pkdup(float x) {
    u64 r; asm("mov.b64 %0, {%1, %1};" : "=l"(r) : "f"(x)); return r;
}
__device__ __forceinline__ void fma2(u64& d, u64 a, u64 b) {
    asm("fma.rn.f32x2 %0, %1, %2, %0;" : "+l"(d) : "l"(a), "l"(b));
}
__device__ __forceinline__ float2 un2(u64 v) {
    float2 f; asm("mov.b64 {%0, %1}, %2;" : "=f"(f.x), "=f"(f.y) : "l"(v));
    return f;
}
__device__ __forceinline__ unsigned ldacq(const unsigned* p) {
    unsigned v;
    asm volatile("ld.acquire.gpu.global.u32 %0, [%1];" : "=r"(v) : "l"(p));
    return v;
}
__device__ __forceinline__ void redrel(unsigned* p) {
    asm volatile("red.release.gpu.global.add.u32 [%0], %1;"
                 :: "l"(p), "r"(1u) : "memory");
}

// ---------------------------------------------------------------------------
// Kernel 1: xproj[s][b][h] = sum_e X[b][s][e] * Wax[h][e] + ba[h]  (as R11)
// ---------------------------------------------------------------------------
__global__ __launch_bounds__(256) void xproj_kernel(
    const float* __restrict__ X, const float* __restrict__ Wax,
    const float* __restrict__ ba, float* __restrict__ out)
{
    __shared__ float As[16][128];
    __shared__ float Bs[16][128];

    const int tid = threadIdx.x;
    const int r0 = blockIdx.x * 128;
    const int h0 = blockIdx.y * 128;

    const int lr = tid >> 1;
    const int lk = (tid & 1) * 8;
    const int r  = r0 + lr;
    const float* Aptr = X + (size_t)(r & (BATCH - 1)) * (SEQ * EMB)
                          + (size_t)(r >> 6) * EMB + lk;
    const float* Bptr = Wax + (size_t)(h0 + lr) * EMB + lk;

    const int tm0 = (tid >> 4) * 4;
    const int tn0 = (tid & 15) * 4;

    u64 acc[8][4];
#pragma unroll
    for (int i = 0; i < 8; i++)
#pragma unroll
        for (int p = 0; p < 4; p++) acc[i][p] = 0ull;

    for (int k0 = 0; k0 < EMB; k0 += 16) {
        float4 a0 = *(const float4*)(Aptr + k0);
        float4 a1 = *(const float4*)(Aptr + k0 + 4);
        float4 b0 = *(const float4*)(Bptr + k0);
        float4 b1 = *(const float4*)(Bptr + k0 + 4);
        As[lk + 0][lr] = a0.x; As[lk + 1][lr] = a0.y;
        As[lk + 2][lr] = a0.z; As[lk + 3][lr] = a0.w;
        As[lk + 4][lr] = a1.x; As[lk + 5][lr] = a1.y;
        As[lk + 6][lr] = a1.z; As[lk + 7][lr] = a1.w;
        Bs[lk + 0][lr] = b0.x; Bs[lk + 1][lr] = b0.y;
        Bs[lk + 2][lr] = b0.z; Bs[lk + 3][lr] = b0.w;
        Bs[lk + 4][lr] = b1.x; Bs[lk + 5][lr] = b1.y;
        Bs[lk + 6][lr] = b1.z; Bs[lk + 7][lr] = b1.w;
        __syncthreads();

#pragma unroll
        for (int k = 0; k < 16; k++) {
            float4 av0 = *(const float4*)&As[k][tm0];
            float4 av1 = *(const float4*)&As[k][tm0 + 64];
            ulonglong2 wA = *(const ulonglong2*)&Bs[k][tn0];
            ulonglong2 wB = *(const ulonglong2*)&Bs[k][tn0 + 64];
            float ar[8] = {av0.x, av0.y, av0.z, av0.w, av1.x, av1.y, av1.z, av1.w};
#pragma unroll
            for (int i = 0; i < 8; i++) {
                u64 ai = pkdup(ar[i]);
                fma2(acc[i][0], ai, wA.x);
                fma2(acc[i][1], ai, wA.y);
                fma2(acc[i][2], ai, wB.x);
                fma2(acc[i][3], ai, wB.y);
            }
        }
        __syncthreads();
    }

    float bav[8];
#pragma unroll
    for (int j = 0; j < 4; j++) {
        bav[j]     = ba[h0 + tn0 + j];
        bav[4 + j] = ba[h0 + tn0 + 64 + j];
    }
#pragma unroll
    for (int gi = 0; gi < 2; gi++) {
#pragma unroll
        for (int ii = 0; ii < 4; ii++) {
            int i = gi * 4 + ii;
            int row = r0 + tm0 + gi * 64 + ii;
            float* o = out + (size_t)row * HID + h0;
            float2 p0 = un2(acc[i][0]), p1 = un2(acc[i][1]);
            float2 p2 = un2(acc[i][2]), p3 = un2(acc[i][3]);
            *(float4*)(o + tn0)      = make_float4(p0.x + bav[0], p0.y + bav[1],
                                                   p1.x + bav[2], p1.y + bav[3]);
            *(float4*)(o + tn0 + 64) = make_float4(p2.x + bav[4], p2.y + bav[5],
                                                   p3.x + bav[6], p3.y + bav[7]);
        }
    }
}

// ---------------------------------------------------------------------------
// Kernel 2: persistent recurrence, WARP-AUTONOMOUS batch-group pipelines.
// CTA bi: h-tile ht=bi>>3 (64 h), k-slice ks=bi&7 (128 k), group g=ht>>1.
// Warp w owns batch-group w (rows 8w..8w+7): an independent recurrence chain.
// Per warp per step (no __syncthreads in the loop):
//   wait ca[ks][w]>=16s (stage dep) & ca[g][w]>=16s (partial overwrite ok)
//   stage a_{s-1}[8w..8w+7][k-slice] -> private smem (k-major [128][8])
//   compute 8b x 64h partials (f32x2), STG; release cp[g][w]
//   wait cp[g][w]>=16s; phase2 own (g,w) slice: tanh(xp+sum8); release ca[g][w]
// 8 chains per SM self-stagger; polls/LDG latency hide under other warps.
// ---------------------------------------------------------------------------
__global__ __launch_bounds__(256) void rnn_persistent(
    const float* __restrict__ Waa, float* __restrict__ outs, int write_hidden)
{
    extern __shared__ float sm[];
    float* Ws = sm;                           // [128][64]

    const int tid = threadIdx.x;
    const int bi  = blockIdx.x;
    const int ht  = bi >> 3;                  // 0..15
    const int ks  = bi & 7;                   // 0..7
    const int g   = ht >> 1;                  // 0..7
    const int h0  = ht * 64;
    const int k0  = ks * 128;
    const int w   = tid >> 5;                 // warp = batch-group 0..7
    const int l   = tid & 31;

    float* Asw = sm + 128 * 64 + w * (128 * 8);   // private [128][8]

    unsigned* ca_own = g_sync + (g * 8 + w) * 16;
    unsigned* ca_ks  = g_sync + (ks * 8 + w) * 16;
    unsigned* cp_own = g_sync + 2048 + (g * 8 + w) * 16;

    // Load W slice once: Ws[k][h] = Waa[h0+h][k0+k]
    {
        const int h  = tid & 63;
        const int kg = tid >> 6;
        const float* wrow = Waa + (size_t)(h0 + h) * HID + k0 + kg * 32;
#pragma unroll
        for (int j = 0; j < 8; j++) {
            float4 wv = *(const float4*)(wrow + j * 4);
            int k = kg * 32 + j * 4;
            Ws[(k + 0) * 64 + h] = wv.x; Ws[(k + 1) * 64 + h] = wv.y;
            Ws[(k + 2) * 64 + h] = wv.z; Ws[(k + 3) * 64 + h] = wv.w;
        }
    }
    __syncthreads();

    const int hh = 2 * l;                     // h-pair within 64
    // staging map: lane -> (b' = l&7, k base = (l>>3)*4), 8 float4 each
    const int sbp = l & 7;
    const int skb = (l >> 3) * 4;
    // phase2 map: element (b = 8w + (cg>>1), h = 128g + (cg&1)*64 + hh)
    const int cg  = ((ht & 1) << 3) | ks;     // CTA index within group, 0..15
    const size_t p2off = (size_t)(8 * w + (cg >> 1)) * HID
                       + (size_t)g * 128 + (cg & 1) * 64 + hh;

    for (int s = 0; s < SEQ; s++) {
        // prefetch own xproj element (only we ever write this element)
        float2 xp = *(const float2*)(outs + (size_t)s * BH + p2off);

        if (s > 0) {
            const unsigned t = 16u * (unsigned)s;
            if (l == 0) {
                while (ldacq(ca_ks) < t) { }
                if (ca_own != ca_ks) while (ldacq(ca_own) < t) { }
            }
            __syncwarp();

            // ---- stage a_{s-1}[8 rows][128 k] into private k-major smem
            const float* src = outs + (size_t)(s - 1) * BH
                             + (size_t)(8 * w + sbp) * HID + k0 + skb;
#pragma unroll
            for (int j = 0; j < 8; j++) {
                float4 v = __ldcg((const float4*)(src + j * 16));
                int k = skb + j * 16;
                Asw[(k + 0) * 8 + sbp] = v.x;
                Asw[(k + 1) * 8 + sbp] = v.y;
                Asw[(k + 2) * 8 + sbp] = v.z;
                Asw[(k + 3) * 8 + sbp] = v.w;
            }
            __syncwarp();

            // ---- compute acc[4 b-pairs][2 h] over 128 k
            u64 acc[4][2];
#pragma unroll
            for (int i = 0; i < 4; i++) { acc[i][0] = 0ull; acc[i][1] = 0ull; }

#pragma unroll 8
            for (int k = 0; k < 128; k++) {
                ulonglong2 aA = *(const ulonglong2*)(Asw + k * 8);      // b0..b3
                ulonglong2 aB = *(const ulonglong2*)(Asw + k * 8 + 4);  // b4..b7
                float2 wv = *(const float2*)(Ws + k * 64 + hh);
                u64 w0 = pkdup(wv.x);
                u64 w1 = pkdup(wv.y);
                fma2(acc[0][0], aA.x, w0); fma2(acc[0][1], aA.x, w1);
                fma2(acc[1][0], aA.y, w0); fma2(acc[1][1], aA.y, w1);
                fma2(acc[2][0], aB.x, w0); fma2(acc[2][1], aB.x, w1);
                fma2(acc[3][0], aB.y, w0); fma2(acc[3][1], aB.y, w1);
            }

            // ---- write partials: g_partial[ks][8w+row][h0+hh..+1]
            float* gp = g_partial + (size_t)ks * BH
                      + (size_t)(8 * w) * HID + h0 + hh;
#pragma unroll
            for (int bp = 0; bp < 4; bp++) {
                float2 ev = un2(acc[bp][0]);
                float2 ov = un2(acc[bp][1]);
                *(float2*)(gp + (size_t)(2 * bp)     * HID) = make_float2(ev.x, ov.x);
                *(float2*)(gp + (size_t)(2 * bp + 1) * HID) = make_float2(ev.y, ov.y);
            }
            __syncwarp();
            if (l == 0) {
                redrel(cp_own);
                while (ldacq(cp_own) < t) { }
            }
            __syncwarp();
        }

        // ---- phase2: own (g, w) slice, one float2 per lane
        {
            float2 v = xp;
            if (s > 0) {
                const float* pp = g_partial + p2off;
#pragma unroll
                for (int p = 0; p < KSLICES; p++) {
                    float2 q = __ldcg((const float2*)(pp + (size_t)p * BH));
                    v.x += q.x; v.y += q.y;
                }
            }
            v.x = tanhf(v.x); v.y = tanhf(v.y);
            *(float2*)(outs + (size_t)s * BH + p2off) = v;
            if (write_hidden && s == SEQ - 1)
                *(float2*)(outs + (size_t)SBH + p2off) = v;
        }
        __syncwarp();
        if (l == 0) redrel(ca_own);
    }
}

// ---------------------------------------------------------------------------
// Launch. Inputs: X [B,S,E] f32, W_ax [H,E] f32, W_aa [H,H] f32, b_a [H] f32.
// Output: outputs [S,B,H] then hidden [B,H].
// ---------------------------------------------------------------------------
extern "C" void kernel_launch(void* const* d_in, const int* in_sizes, int n_in,
                              void* d_out, int out_size) {
    (void)in_sizes; (void)n_in;
    const float* X   = (const float*)d_in[0];
    const float* Wax = (const float*)d_in[1];
    const float* Waa = (const float*)d_in[2];
    const float* ba  = (const float*)d_in[3];
    float* out = (float*)d_out;

    cudaFuncSetAttribute(rnn_persistent,
                         cudaFuncAttributeMaxDynamicSharedMemorySize, RNN_SMEM);

    void* sp = nullptr;
    cudaGetSymbolAddress(&sp, g_sync);
    cudaMemsetAsync(sp, 0, 4096 * sizeof(unsigned), 0);

    dim3 g1((SEQ * BATCH) / 128, HID / 128);
    xproj_kernel<<<g1, 256>>>(X, Wax, ba, out);

    int write_hidden = (out_size >= (int)(SBH + BH)) ? 1 : 0;
    rnn_persistent<<<NBLOCKS, 256, RNN_SMEM>>>(Waa, out, write_hidden);
}

// round 13
// speedup vs baseline: 1.1637x; 1.1637x over previous
#include <cuda_runtime.h>
#include <math.h>

#define BATCH 64
#define SEQ   512
#define EMB   512
#define HID   1024
#define BH    (BATCH * HID)        // 65536
#define SBH   (SEQ * BH)           // 33554432
#define KSLICES 8
#define NBLOCKS 128                // 16 h-tiles (64h) x 8 k-slices (128k)

// dynamic smem: Ws[128][64] 32KB + Asb[128][32] swizzled 16KB + rbuf[8][128]u64 8KB
#define RNN_SMEM (8192 * 4 + 4096 * 4 + 1024 * 8)   // 57344

typedef unsigned long long u64;

// Per-step K-split partials: [KSLICES][BATCH][HID] = 2 MB (chains use disjoint b)
__device__ float g_partial[KSLICES * BH];
// Counters: ca[c][g] at ((c*8+g)*16), cp[c][g] at 512+((c*8+g)*16)  (64B apart)
__device__ unsigned g_sync[1024];

// ---------------- packed fp32x2 helpers (sm_103a) ---------------------------
__device__ __forceinline__ u64 pkdup(float x) {
    u64 r; asm("mov.b64 %0, {%1, %1};" : "=l"(r) : "f"(x)); return r;
}
__device__ __forceinline__ void fma2(u64& d, u64 a, u64 b) {
    asm("fma.rn.f32x2 %0, %1, %2, %0;" : "+l"(d) : "l"(a), "l"(b));
}
__device__ __forceinline__ u64 add2(u64 a, u64 b) {
    u64 r; asm("add.rn.f32x2 %0, %1, %2;" : "=l"(r) : "l"(a), "l"(b)); return r;
}
__device__ __forceinline__ float2 un2(u64 v) {
    float2 f; asm("mov.b64 {%0, %1}, %2;" : "=f"(f.x), "=f"(f.y) : "l"(v));
    return f;
}
__device__ __forceinline__ unsigned ldacq(const unsigned* p) {
    unsigned v;
    asm volatile("ld.acquire.gpu.global.u32 %0, [%1];" : "=r"(v) : "l"(p));
    return v;
}
__device__ __forceinline__ void redrel(unsigned* p) {
    asm volatile("red.release.gpu.global.add.u32 [%0], %1;"
                 :: "l"(p), "r"(1u) : "memory");
}

// ---------------------------------------------------------------------------
// Kernel 1: xproj[s][b][h] = sum_e X[b][s][e] * Wax[h][e] + ba[h]  (as R11)
// ---------------------------------------------------------------------------
__global__ __launch_bounds__(256) void xproj_kernel(
    const float* __restrict__ X, const float* __restrict__ Wax,
    const float* __restrict__ ba, float* __restrict__ out)
{
    __shared__ float As[16][128];
    __shared__ float Bs[16][128];

    const int tid = threadIdx.x;
    const int r0 = blockIdx.x * 128;
    const int h0 = blockIdx.y * 128;

    const int lr = tid >> 1;
    const int lk = (tid & 1) * 8;
    const int r  = r0 + lr;
    const float* Aptr = X + (size_t)(r & (BATCH - 1)) * (SEQ * EMB)
                          + (size_t)(r >> 6) * EMB + lk;
    const float* Bptr = Wax + (size_t)(h0 + lr) * EMB + lk;

    const int tm0 = (tid >> 4) * 4;
    const int tn0 = (tid & 15) * 4;

    u64 acc[8][4];
#pragma unroll
    for (int i = 0; i < 8; i++)
#pragma unroll
        for (int p = 0; p < 4; p++) acc[i][p] = 0ull;

    for (int k0 = 0; k0 < EMB; k0 += 16) {
        float4 a0 = *(const float4*)(Aptr + k0);
        float4 a1 = *(const float4*)(Aptr + k0 + 4);
        float4 b0 = *(const float4*)(Bptr + k0);
        float4 b1 = *(const float4*)(Bptr + k0 + 4);
        As[lk + 0][lr] = a0.x; As[lk + 1][lr] = a0.y;
        As[lk + 2][lr] = a0.z; As[lk + 3][lr] = a0.w;
        As[lk + 4][lr] = a1.x; As[lk + 5][lr] = a1.y;
        As[lk + 6][lr] = a1.z; As[lk + 7][lr] = a1.w;
        Bs[lk + 0][lr] = b0.x; Bs[lk + 1][lr] = b0.y;
        Bs[lk + 2][lr] = b0.z; Bs[lk + 3][lr] = b0.w;
        Bs[lk + 4][lr] = b1.x; Bs[lk + 5][lr] = b1.y;
        Bs[lk + 6][lr] = b1.z; Bs[lk + 7][lr] = b1.w;
        __syncthreads();

#pragma unroll
        for (int k = 0; k < 16; k++) {
            float4 av0 = *(const float4*)&As[k][tm0];
            float4 av1 = *(const float4*)&As[k][tm0 + 64];
            ulonglong2 wA = *(const ulonglong2*)&Bs[k][tn0];
            ulonglong2 wB = *(const ulonglong2*)&Bs[k][tn0 + 64];
            float ar[8] = {av0.x, av0.y, av0.z, av0.w, av1.x, av1.y, av1.z, av1.w};
#pragma unroll
            for (int i = 0; i < 8; i++) {
                u64 ai = pkdup(ar[i]);
                fma2(acc[i][0], ai, wA.x);
                fma2(acc[i][1], ai, wA.y);
                fma2(acc[i][2], ai, wB.x);
                fma2(acc[i][3], ai, wB.y);
            }
        }
        __syncthreads();
    }

    float bav[8];
#pragma unroll
    for (int j = 0; j < 4; j++) {
        bav[j]     = ba[h0 + tn0 + j];
        bav[4 + j] = ba[h0 + tn0 + 64 + j];
    }
#pragma unroll
    for (int gi = 0; gi < 2; gi++) {
#pragma unroll
        for (int ii = 0; ii < 4; ii++) {
            int i = gi * 4 + ii;
            int row = r0 + tm0 + gi * 64 + ii;
            float* o = out + (size_t)row * HID + h0;
            float2 p0 = un2(acc[i][0]), p1 = un2(acc[i][1]);
            float2 p2 = un2(acc[i][2]), p3 = un2(acc[i][3]);
            *(float4*)(o + tn0)      = make_float4(p0.x + bav[0], p0.y + bav[1],
                                                   p1.x + bav[2], p1.y + bav[3]);
            *(float4*)(o + tn0 + 64) = make_float4(p2.x + bav[4], p2.y + bav[5],
                                                   p3.x + bav[6], p3.y + bav[7]);
        }
    }
}

// ---------------------------------------------------------------------------
// Kernel 2: persistent recurrence, TWO interleaved b-half chains per CTA.
// CTA bi: h-tile ht=bi>>3 (64 h), k-slice ks=bi&7 (128 k), group g=ht>>1.
// Chain c owns batch rows [32c, 32c+32) — fully independent recurrence.
// Per step: frontA, frontB, phase2A, phase2B. Each chain's release->acquire
// round hides under the other chain's ~2500-cyc front.
// front(c): wait ca[c][ks]>=16s & ca[c][g]>=16s; stage a_{s-1}[b-half][k0..+128)
//   into XOR-swizzled k-major smem; warps split k in halves (4+4), f32x2
//   compute acc[4bp][2h]; smem reduce of k-halves; STG partials; rel cp[c][g].
// phase2(c): wait cp[c][g]>=16s; tanh(xp + sum8 partials); STG a_s; rel ca[c][g].
// ---------------------------------------------------------------------------
__global__ __launch_bounds__(256, 1) void rnn_persistent(
    const float* __restrict__ Waa, float* __restrict__ outs, int write_hidden)
{
    extern __shared__ float sm[];
    float* Ws   = sm;                          // [128][64]
    float* Asb  = sm + 8192;                   // [128][32] swizzled
    u64*   rbuf = (u64*)(sm + 8192 + 4096);    // [8][128]

    const int tid = threadIdx.x;
    const int bi  = blockIdx.x;
    const int ht  = bi >> 3;                   // 0..15
    const int ks  = bi & 7;                    // 0..7
    const int g   = ht >> 1;                   // 0..7
    const int h0  = ht * 64;
    const int k0  = ks * 128;

    unsigned* ca_ks[2] = { g_sync + (0 * 8 + ks) * 16,
                           g_sync + (1 * 8 + ks) * 16 };
    unsigned* ca_g[2]  = { g_sync + (0 * 8 + g) * 16,
                           g_sync + (1 * 8 + g) * 16 };
    unsigned* cp_g[2]  = { g_sync + 512 + (0 * 8 + g) * 16,
                           g_sync + 512 + (1 * 8 + g) * 16 };

    // Load W slice once: Ws[k][h] = Waa[h0+h][k0+k]
    {
        const int h  = tid & 63;
        const int kg = tid >> 6;
        const float* wrow = Waa + (size_t)(h0 + h) * HID + k0 + kg * 32;
#pragma unroll
        for (int j = 0; j < 8; j++) {
            float4 wv = *(const float4*)(wrow + j * 4);
            int k = kg * 32 + j * 4;
            Ws[(k + 0) * 64 + h] = wv.x; Ws[(k + 1) * 64 + h] = wv.y;
            Ws[(k + 2) * 64 + h] = wv.z; Ws[(k + 3) * 64 + h] = wv.w;
        }
    }
    __syncthreads();

    // compute map: warp w: b-octet o=w&3 (8 b), k-half kh=w>>2; lane: 2 h
    const int w  = tid >> 5;
    const int l  = tid & 31;
    const int o  = w & 3;
    const int kh = w >> 2;
    const int hh = 2 * l;
    // staging map: thread -> b_local = tid>>3 (0..31), k-chunk km = tid&7 (16 k)
    const int sb  = tid >> 3;
    const int scb = sb >> 2;       // 4-b chunk index 0..7
    const int sb3 = sb & 3;
    const int skm = tid & 7;
    // phase2 map: element (b = 32c + p2b, h = 128g + (tid&127))
    const int cg   = ((ht & 1) << 3) | ks;         // CTA index in group 0..15
    const int p2b  = (cg << 1) | (tid >> 7);       // 0..31
    const int p2h  = g * 128 + (tid & 127);
    const size_t p2rel = (size_t)p2b * HID + p2h;  // + 32c*HID per chain

    for (int s = 0; s < SEQ; s++) {
        const size_t sbase = (size_t)s * BH;
        // prefetch xproj for both chains (only our own phase2 writes these)
        float xp[2];
        xp[0] = outs[sbase + p2rel];
        xp[1] = outs[sbase + (size_t)32 * HID + p2rel];

        if (s > 0) {
            const unsigned t = 16u * (unsigned)s;

            // ================= fronts for both chains =================
#pragma unroll 1
            for (int c = 0; c < 2; c++) {
                if (tid == 0) {
                    while (ldacq(ca_ks[c]) < t) { }
                    if (g != ks) while (ldacq(ca_g[c]) < t) { }
                }
                __syncthreads();

                // ---- stage a_{s-1}[32c+sb][k0 + skm*16 .. +16)
                const float* src = outs + (size_t)(s - 1) * BH
                                 + (size_t)(32 * c + sb) * HID + k0 + skm * 16;
                float4 t4[4];
#pragma unroll
                for (int j = 0; j < 4; j++)
                    t4[j] = __ldcg((const float4*)(src + j * 4));
                // Asb free: all reads finished before the syncs above
#pragma unroll
                for (int j4 = 0; j4 < 4; j4++) {
                    float vv[4] = {t4[j4].x, t4[j4].y, t4[j4].z, t4[j4].w};
#pragma unroll
                    for (int i = 0; i < 4; i++) {
                        int kl = skm * 16 + j4 * 4 + i;
                        int sw = ((j4 * 4 + i) & 7) ^ skm;   // (kl&7)^(kl>>4)
                        Asb[kl * 32 + ((scb ^ sw) << 2) + sb3] = vv[i];
                    }
                }
                __syncthreads();

                // ---- compute acc[4 b-pairs][2 h] over this warp's 64 k
                u64 acc[4][2];
#pragma unroll
                for (int i = 0; i < 4; i++) { acc[i][0] = 0ull; acc[i][1] = 0ull; }

                const int kstart = kh * 64;
                for (int kb = 0; kb < 64; kb += 8) {
                    const int kk = kstart + kb;
                    const int cbase = (2 * o) ^ ((kk >> 4) & 7);
#pragma unroll
                    for (int u = 0; u < 8; u++) {
                        const int k = kk + u;
                        const int c0 = cbase ^ u;
                        const float* base = Asb + k * 32;
                        ulonglong2 pa = *(const ulonglong2*)(base + (c0 << 2));
                        ulonglong2 pb = *(const ulonglong2*)(base + ((c0 ^ 1) << 2));
                        float2 wv = *(const float2*)(Ws + k * 64 + hh);
                        u64 w0 = pkdup(wv.x);
                        u64 w1 = pkdup(wv.y);
                        fma2(acc[0][0], pa.x, w0); fma2(acc[0][1], pa.x, w1);
                        fma2(acc[1][0], pa.y, w0); fma2(acc[1][1], pa.y, w1);
                        fma2(acc[2][0], pb.x, w0); fma2(acc[2][1], pb.x, w1);
                        fma2(acc[3][0], pb.y, w0); fma2(acc[3][1], pb.y, w1);
                    }
                }
                __syncthreads();   // Asb reads done; accs final

                // ---- fold k-halves: upper warps publish, lower warps combine
                if (w >= 4) {
#pragma unroll
                    for (int bp = 0; bp < 4; bp++) {
                        rbuf[(bp * 2 + 0) * 128 + (tid & 127)] = acc[bp][0];
                        rbuf[(bp * 2 + 1) * 128 + (tid & 127)] = acc[bp][1];
                    }
                }
                __syncthreads();
                if (w < 4) {
                    float* gp = g_partial + (size_t)ks * BH
                              + (size_t)(32 * c + o * 8) * HID + h0 + hh;
#pragma unroll
                    for (int bp = 0; bp < 4; bp++) {
                        u64 s0 = add2(acc[bp][0], rbuf[(bp * 2 + 0) * 128 + tid]);
                        u64 s1 = add2(acc[bp][1], rbuf[(bp * 2 + 1) * 128 + tid]);
                        float2 ev = un2(s0);     // h=hh   for (b even, b odd)
                        float2 ov = un2(s1);     // h=hh+1
                        *(float2*)(gp + (size_t)(2 * bp)     * HID)
                            = make_float2(ev.x, ov.x);
                        *(float2*)(gp + (size_t)(2 * bp + 1) * HID)
                            = make_float2(ev.y, ov.y);
                    }
                }
                __syncthreads();
                if (tid == 0) redrel(cp_g[c]);
            }
        }

        // ================= phase2 for both chains =================
#pragma unroll 1
        for (int c = 0; c < 2; c++) {
            if (s > 0) {
                if (tid == 0) {
                    const unsigned t = 16u * (unsigned)s;
                    while (ldacq(cp_g[c]) < t) { }
                }
                __syncthreads();
            }
            float v = xp[c];
            const size_t off = (size_t)(32 * c) * HID + p2rel;
            if (s > 0) {
                const float* pp = g_partial + off;
#pragma unroll
                for (int p = 0; p < KSLICES; p++)
                    v += __ldcg(pp + (size_t)p * BH);
            }
            v = tanhf(v);
            outs[sbase + off] = v;
            if (write_hidden && s == SEQ - 1) outs[(size_t)SBH + off] = v;
            __syncthreads();
            if (tid == 0) redrel(ca_g[c]);
        }
    }
}

// ---------------------------------------------------------------------------
// Launch. Inputs: X [B,S,E] f32, W_ax [H,E] f32, W_aa [H,H] f32, b_a [H] f32.
// Output: outputs [S,B,H] then hidden [B,H].
// ---------------------------------------------------------------------------
extern "C" void kernel_launch(void* const* d_in, const int* in_sizes, int n_in,
                              void* d_out, int out_size) {
    (void)in_sizes; (void)n_in;
    const float* X   = (const float*)d_in[0];
    const float* Wax = (const float*)d_in[1];
    const float* Waa = (const float*)d_in[2];
    const float* ba  = (const float*)d_in[3];
    float* out = (float*)d_out;

    cudaFuncSetAttribute(rnn_persistent,
                         cudaFuncAttributeMaxDynamicSharedMemorySize, RNN_SMEM);

    void* sp = nullptr;
    cudaGetSymbolAddress(&sp, g_sync);
    cudaMemsetAsync(sp, 0, 1024 * sizeof(unsigned), 0);

    dim3 g1((SEQ * BATCH) / 128, HID / 128);
    xproj_kernel<<<g1, 256>>>(X, Wax, ba, out);

    int write_hidden = (out_size >= (int)(SBH + BH)) ? 1 : 0;
    rnn_persistent<<<NBLOCKS, 256, RNN_SMEM>>>(Waa, out, write_hidden);
}